// round 1
// baseline (speedup 1.0000x reference)
#include <cuda_runtime.h>
#include <math.h>

// Problem constants
#define LNUM 6
#define BSZ  4
#define TSEQ 1024
#define DDIM 1024
#define HNUM 16
#define HDIM 64
#define DFF  4096
#define BT   4096          // BSZ*TSEQ
#define RMS_EPS 1.1920929e-07f
#define LN_EPS  1e-5f

// ---------------- scratch (static device arrays; no allocations) -------------
__device__ float g_hattn[(size_t)BT * DDIM];          // 16 MB
__device__ float g_x    [(size_t)BT * DDIM];          // 16 MB  (LN out / reused)
__device__ float g_qkv  [(size_t)BT * 3 * DDIM];      // 48 MB
__device__ float g_ctx  [(size_t)BT * DDIM];          // 16 MB
__device__ float g_vlat [(size_t)BT * DDIM];          // 16 MB
__device__ float g_hmlp [(size_t)BT * DDIM];          // 16 MB
__device__ float g_y    [(size_t)BT * DDIM];          // 16 MB
__device__ float g_ffn1 [(size_t)BT * DFF];           // 64 MB

__device__ __forceinline__ float gelu_exact(float v) {
    return 0.5f * v * (1.0f + erff(v * 0.70710678118654752f));
}

// ---------------- depth-softmax attention residual ---------------------------
// One block per token (B*T blocks, 256 threads, 4 dims/thread).
// K = rmsnorm(V); logit_l = dot(proj, K_l); w = softmax_l; out = sum_l w_l V_l
template<int LC>
__global__ __launch_bounds__(256)
void far_kernel(const float* __restrict__ src, const float* __restrict__ extra,
                const float* __restrict__ proj, const float* __restrict__ rmsw,
                float* __restrict__ out)
{
    int token = blockIdx.x;
    int tid   = threadIdx.x;
    __shared__ float buf[16];

    float pw[4];
#pragma unroll
    for (int i = 0; i < 4; i++) {
        int d = tid + 256 * i;
        pw[i] = proj[d] * rmsw[d];
    }

    float v[LC][4];
    float logit[LC];

#pragma unroll
    for (int l = 0; l < LC; l++) {
        const float* p = (l < LNUM) ? (src + ((size_t)l * BT + token) * DDIM)
                                    : (extra + (size_t)token * DDIM);
        float ss = 0.f, dw = 0.f;
#pragma unroll
        for (int i = 0; i < 4; i++) {
            float xv = p[tid + 256 * i];
            v[l][i] = xv;
            ss += xv * xv;
            dw += pw[i] * xv;
        }
#pragma unroll
        for (int o = 16; o; o >>= 1) {
            ss += __shfl_xor_sync(0xffffffffu, ss, o);
            dw += __shfl_xor_sync(0xffffffffu, dw, o);
        }
        int lane = tid & 31, w = tid >> 5;
        __syncthreads();
        if (lane == 0) { buf[w] = ss; buf[8 + w] = dw; }
        __syncthreads();
        float sst = 0.f, dwt = 0.f;
#pragma unroll
        for (int j = 0; j < 8; j++) { sst += buf[j]; dwt += buf[8 + j]; }
        logit[l] = dwt * rsqrtf(sst * (1.0f / DDIM) + RMS_EPS);
    }

    float mx = logit[0];
#pragma unroll
    for (int l = 1; l < LC; l++) mx = fmaxf(mx, logit[l]);
    float s = 0.f;
    float wl[LC];
#pragma unroll
    for (int l = 0; l < LC; l++) { wl[l] = __expf(logit[l] - mx); s += wl[l]; }
    float inv = 1.0f / s;

#pragma unroll
    for (int i = 0; i < 4; i++) {
        float o = 0.f;
#pragma unroll
        for (int l = 0; l < LC; l++) o += wl[l] * v[l][i];
        out[(size_t)token * DDIM + tid + 256 * i] = o * inv;
    }
}

// ---------------- LayerNorm ---------------------------------------------------
__global__ __launch_bounds__(256)
void ln_kernel(const float* __restrict__ in, const float* __restrict__ w,
               const float* __restrict__ b, float* __restrict__ out)
{
    int token = blockIdx.x;
    int tid   = threadIdx.x;
    __shared__ float buf[16];

    float x[4];
    float s = 0.f, ss = 0.f;
#pragma unroll
    for (int i = 0; i < 4; i++) {
        float xv = in[(size_t)token * DDIM + tid + 256 * i];
        x[i] = xv; s += xv; ss += xv * xv;
    }
#pragma unroll
    for (int o = 16; o; o >>= 1) {
        s  += __shfl_xor_sync(0xffffffffu, s, o);
        ss += __shfl_xor_sync(0xffffffffu, ss, o);
    }
    int lane = tid & 31, wp = tid >> 5;
    __syncthreads();
    if (lane == 0) { buf[wp] = s; buf[8 + wp] = ss; }
    __syncthreads();
    float st = 0.f, sst = 0.f;
#pragma unroll
    for (int j = 0; j < 8; j++) { st += buf[j]; sst += buf[8 + j]; }
    float mu  = st * (1.0f / DDIM);
    float var = sst * (1.0f / DDIM) - mu * mu;
    float r   = rsqrtf(var + LN_EPS);
#pragma unroll
    for (int i = 0; i < 4; i++) {
        int d = tid + 256 * i;
        out[(size_t)token * DDIM + d] = (x[i] - mu) * r * w[d] + b[d];
    }
}

// ---------------- fp32 tiled GEMM: C = A[M,K] @ B[N,K]^T + bias (+res, +gelu) -
// 128x128x8 tile, 256 threads, 8x8 register tile per thread.
template<int ACT, bool RES>
__global__ __launch_bounds__(256, 2)
void gemm_kernel(const float* __restrict__ A, const float* __restrict__ Bm,
                 const float* __restrict__ bias, const float* __restrict__ res,
                 float* __restrict__ C, int M, int N, int K)
{
    __shared__ float As[8][128];
    __shared__ float Bs[8][128];

    int bm  = blockIdx.y * 128;
    int bn  = blockIdx.x * 128;
    int tid = threadIdx.x;
    int tm  = (tid >> 4) << 3;      // 0..120
    int tn  = (tid & 15) << 3;      // 0..120

    int ar = tid >> 1;              // 0..127
    int ac = (tid & 1) << 2;        // 0 or 4
    const float* Aptr = A  + (size_t)(bm + ar) * K + ac;
    const float* Bptr = Bm + (size_t)(bn + ar) * K + ac;

    float acc[64];
#pragma unroll
    for (int i = 0; i < 64; i++) acc[i] = 0.f;

    for (int k0 = 0; k0 < K; k0 += 8) {
        float4 av = *(const float4*)(Aptr + k0);
        float4 bv = *(const float4*)(Bptr + k0);
        __syncthreads();
        As[ac + 0][ar] = av.x; As[ac + 1][ar] = av.y;
        As[ac + 2][ar] = av.z; As[ac + 3][ar] = av.w;
        Bs[ac + 0][ar] = bv.x; Bs[ac + 1][ar] = bv.y;
        Bs[ac + 2][ar] = bv.z; Bs[ac + 3][ar] = bv.w;
        __syncthreads();
#pragma unroll
        for (int kk = 0; kk < 8; kk++) {
            float a[8], b[8];
            *(float4*)&a[0] = *(const float4*)&As[kk][tm];
            *(float4*)&a[4] = *(const float4*)&As[kk][tm + 4];
            *(float4*)&b[0] = *(const float4*)&Bs[kk][tn];
            *(float4*)&b[4] = *(const float4*)&Bs[kk][tn + 4];
#pragma unroll
            for (int i = 0; i < 8; i++)
#pragma unroll
                for (int j = 0; j < 8; j++)
                    acc[i * 8 + j] += a[i] * b[j];
        }
    }

#pragma unroll
    for (int i = 0; i < 8; i++) {
        size_t row = (size_t)(bm + tm + i);
        float tmp[8];
#pragma unroll
        for (int j = 0; j < 8; j++) {
            int col = bn + tn + j;
            float vv = acc[i * 8 + j] + bias[col];
            if (ACT == 1) vv = gelu_exact(vv);
            if (RES) vv += res[row * N + col];
            tmp[j] = vv;
        }
        *(float4*)&C[row * N + bn + tn]     = make_float4(tmp[0], tmp[1], tmp[2], tmp[3]);
        *(float4*)&C[row * N + bn + tn + 4] = make_float4(tmp[4], tmp[5], tmp[6], tmp[7]);
    }
}

// ---------------- causal flash attention (fp32) -------------------------------
// grid (T/64, B*H), block 256. Thread (r = tid/4, c = tid%4): q-row r of the
// 64-row q tile, dims [c*16, c*16+16). K/V tiles staged in smem.
__global__ __launch_bounds__(256, 2)
void flash_kernel(const float* __restrict__ qkv, float* __restrict__ ctx)
{
    __shared__ float Ks[64][64];
    __shared__ float Vs[64][64];

    int qt  = blockIdx.x;
    int bh  = blockIdx.y;
    int b   = bh >> 4;
    int h   = bh & 15;
    int tid = threadIdx.x;
    int r   = tid >> 2;
    int c   = tid & 3;
    int qg  = qt * 64 + r;

    const float* qbase = qkv + ((size_t)b * TSEQ + qg) * (3 * DDIM) + h * HDIM + c * 16;
    float q[16];
#pragma unroll
    for (int i = 0; i < 16; i++) q[i] = qbase[i] * 0.125f;   // 1/sqrt(64)

    float m = -1e30f, l = 0.f;
    float acc[16];
#pragma unroll
    for (int i = 0; i < 16; i++) acc[i] = 0.f;

    int lane  = tid & 31;
    unsigned gmask = 0xFu << (lane & 28);

    int nkt = qt + 1;
    for (int kt = 0; kt < nkt; kt++) {
        __syncthreads();
        {
            int krow = kt * 64 + r;
            const float* kb = qkv + ((size_t)b * TSEQ + krow) * (3 * DDIM) + DDIM + h * HDIM + c * 16;
            const float* vb = kb + DDIM;
#pragma unroll
            for (int i = 0; i < 4; i++) {
                *(float4*)&Ks[r][c * 16 + 4 * i] = *(const float4*)(kb + 4 * i);
                *(float4*)&Vs[r][c * 16 + 4 * i] = *(const float4*)(vb + 4 * i);
            }
        }
        __syncthreads();

        int kmax = (kt == qt) ? (r + 1) : 64;
        for (int kk = 0; kk < kmax; kk++) {
            const float4* kr = (const float4*)&Ks[kk][c * 16];
            float4 k0 = kr[0], k1 = kr[1], k2 = kr[2], k3 = kr[3];
            float s = q[0]*k0.x + q[1]*k0.y + q[2]*k0.z + q[3]*k0.w
                    + q[4]*k1.x + q[5]*k1.y + q[6]*k1.z + q[7]*k1.w
                    + q[8]*k2.x + q[9]*k2.y + q[10]*k2.z + q[11]*k2.w
                    + q[12]*k3.x + q[13]*k3.y + q[14]*k3.z + q[15]*k3.w;
            s += __shfl_xor_sync(gmask, s, 1);
            s += __shfl_xor_sync(gmask, s, 2);

            float mn    = fmaxf(m, s);
            float scale = __expf(m - mn);
            float p     = __expf(s - mn);
            l = l * scale + p;
            m = mn;

            const float4* vr = (const float4*)&Vs[kk][c * 16];
            float4 v0 = vr[0], v1 = vr[1], v2 = vr[2], v3 = vr[3];
            acc[0]  = acc[0]*scale  + p*v0.x;  acc[1]  = acc[1]*scale  + p*v0.y;
            acc[2]  = acc[2]*scale  + p*v0.z;  acc[3]  = acc[3]*scale  + p*v0.w;
            acc[4]  = acc[4]*scale  + p*v1.x;  acc[5]  = acc[5]*scale  + p*v1.y;
            acc[6]  = acc[6]*scale  + p*v1.z;  acc[7]  = acc[7]*scale  + p*v1.w;
            acc[8]  = acc[8]*scale  + p*v2.x;  acc[9]  = acc[9]*scale  + p*v2.y;
            acc[10] = acc[10]*scale + p*v2.z;  acc[11] = acc[11]*scale + p*v2.w;
            acc[12] = acc[12]*scale + p*v3.x;  acc[13] = acc[13]*scale + p*v3.y;
            acc[14] = acc[14]*scale + p*v3.z;  acc[15] = acc[15]*scale + p*v3.w;
        }
    }

    float invl = 1.0f / l;
    float* ob = ctx + ((size_t)b * TSEQ + qg) * DDIM + h * HDIM + c * 16;
#pragma unroll
    for (int i = 0; i < 16; i++) ob[i] = acc[i] * invl;
}

// ---------------- driver ------------------------------------------------------
extern "C" void kernel_launch(void* const* d_in, const int* in_sizes, int n_in,
                              void* d_out, int out_size)
{
    const float* src        = (const float*)d_in[0];
    const float* w_attn     = (const float*)d_in[1];
    const float* rms_attn_w = (const float*)d_in[2];
    const float* w_ffn      = (const float*)d_in[3];
    const float* rms_ffn_w  = (const float*)d_in[4];
    const float* ln_attn_w  = (const float*)d_in[5];
    const float* ln_attn_b  = (const float*)d_in[6];
    const float* ln_ffn_w   = (const float*)d_in[7];
    const float* ln_ffn_b   = (const float*)d_in[8];
    const float* in_proj_w  = (const float*)d_in[9];
    const float* in_proj_b  = (const float*)d_in[10];
    const float* out_proj_w = (const float*)d_in[11];
    const float* out_proj_b = (const float*)d_in[12];
    const float* ffn_w1     = (const float*)d_in[13];
    const float* ffn_b1     = (const float*)d_in[14];
    const float* ffn_w2     = (const float*)d_in[15];
    const float* ffn_b2     = (const float*)d_in[16];
    float* out = (float*)d_out;

    float *hattn, *x, *qkv, *ctx, *vlat, *hmlp, *y, *ffn1;
    cudaGetSymbolAddress((void**)&hattn, g_hattn);
    cudaGetSymbolAddress((void**)&x,     g_x);
    cudaGetSymbolAddress((void**)&qkv,   g_qkv);
    cudaGetSymbolAddress((void**)&ctx,   g_ctx);
    cudaGetSymbolAddress((void**)&vlat,  g_vlat);
    cudaGetSymbolAddress((void**)&hmlp,  g_hmlp);
    cudaGetSymbolAddress((void**)&y,     g_y);
    cudaGetSymbolAddress((void**)&ffn1,  g_ffn1);

    // 1) depth-softmax attention residual over the 6 sources
    far_kernel<6><<<BT, 256>>>(src, nullptr, w_attn, rms_attn_w, hattn);
    // 2) LN + QKV projection
    ln_kernel<<<BT, 256>>>(hattn, ln_attn_w, ln_attn_b, x);
    gemm_kernel<0, false><<<dim3(3 * DDIM / 128, BT / 128), 256>>>(
        x, in_proj_w, in_proj_b, nullptr, qkv, BT, 3 * DDIM, DDIM);
    // causal MHA
    flash_kernel<<<dim3(TSEQ / 64, BSZ * HNUM), 256>>>(qkv, ctx);
    // out projection + residual (v_prev = sources[-1])
    gemm_kernel<0, true><<<dim3(DDIM / 128, BT / 128), 256>>>(
        ctx, out_proj_w, out_proj_b, src + (size_t)(LNUM - 1) * BT * DDIM,
        vlat, BT, DDIM, DDIM);
    // 4) depth-softmax attention residual over 7 layers (sources + v_l_attn)
    far_kernel<7><<<BT, 256>>>(src, vlat, w_ffn, rms_ffn_w, hmlp);
    // 5) LN + FFN (GELU) + final residual
    ln_kernel<<<BT, 256>>>(hmlp, ln_ffn_w, ln_ffn_b, y);
    gemm_kernel<1, false><<<dim3(DFF / 128, BT / 128), 256>>>(
        y, ffn_w1, ffn_b1, nullptr, ffn1, BT, DFF, DDIM);
    gemm_kernel<0, true><<<dim3(DDIM / 128, BT / 128), 256>>>(
        ffn1, ffn_w2, ffn_b2, vlat, out, BT, DDIM, DFF);
}

// round 2
// speedup vs baseline: 1.5425x; 1.5425x over previous
#include <cuda_runtime.h>
#include <cuda_bf16.h>
#include <math.h>

// Problem constants
#define LNUM 6
#define BSZ  4
#define TSEQ 1024
#define DDIM 1024
#define HNUM 16
#define HDIM 64
#define DFF  4096
#define BT   4096          // BSZ*TSEQ
#define RMS_EPS 1.1920929e-07f
#define LN_EPS  1e-5f

// ---------------- scratch (static device arrays; no allocations) -------------
__device__ float g_hattn[(size_t)BT * DDIM];
__device__ float g_x    [(size_t)BT * DDIM];
__device__ float g_qkv  [(size_t)BT * 3 * DDIM];
__device__ float g_ctx  [(size_t)BT * DDIM];
__device__ float g_vlat [(size_t)BT * DDIM];
__device__ float g_hmlp [(size_t)BT * DDIM];
__device__ float g_y    [(size_t)BT * DDIM];
__device__ float g_ffn1 [(size_t)BT * DFF];

__device__ __forceinline__ float gelu_exact(float v) {
    return 0.5f * v * (1.0f + erff(v * 0.70710678118654752f));
}

// ---------------- depth-softmax attention residual ---------------------------
template<int LC>
__global__ __launch_bounds__(256)
void far_kernel(const float* __restrict__ src, const float* __restrict__ extra,
                const float* __restrict__ proj, const float* __restrict__ rmsw,
                float* __restrict__ out)
{
    int token = blockIdx.x;
    int tid   = threadIdx.x;
    __shared__ float buf[16];

    float pw[4];
#pragma unroll
    for (int i = 0; i < 4; i++) {
        int d = tid + 256 * i;
        pw[i] = proj[d] * rmsw[d];
    }

    float v[LC][4];
    float logit[LC];

#pragma unroll
    for (int l = 0; l < LC; l++) {
        const float* p = (l < LNUM) ? (src + ((size_t)l * BT + token) * DDIM)
                                    : (extra + (size_t)token * DDIM);
        float ss = 0.f, dw = 0.f;
#pragma unroll
        for (int i = 0; i < 4; i++) {
            float xv = p[tid + 256 * i];
            v[l][i] = xv;
            ss += xv * xv;
            dw += pw[i] * xv;
        }
#pragma unroll
        for (int o = 16; o; o >>= 1) {
            ss += __shfl_xor_sync(0xffffffffu, ss, o);
            dw += __shfl_xor_sync(0xffffffffu, dw, o);
        }
        int lane = tid & 31, w = tid >> 5;
        __syncthreads();
        if (lane == 0) { buf[w] = ss; buf[8 + w] = dw; }
        __syncthreads();
        float sst = 0.f, dwt = 0.f;
#pragma unroll
        for (int j = 0; j < 8; j++) { sst += buf[j]; dwt += buf[8 + j]; }
        logit[l] = dwt * rsqrtf(sst * (1.0f / DDIM) + RMS_EPS);
    }

    float mx = logit[0];
#pragma unroll
    for (int l = 1; l < LC; l++) mx = fmaxf(mx, logit[l]);
    float s = 0.f;
    float wl[LC];
#pragma unroll
    for (int l = 0; l < LC; l++) { wl[l] = __expf(logit[l] - mx); s += wl[l]; }
    float inv = 1.0f / s;

#pragma unroll
    for (int i = 0; i < 4; i++) {
        float o = 0.f;
#pragma unroll
        for (int l = 0; l < LC; l++) o += wl[l] * v[l][i];
        out[(size_t)token * DDIM + tid + 256 * i] = o * inv;
    }
}

// ---------------- LayerNorm ---------------------------------------------------
__global__ __launch_bounds__(256)
void ln_kernel(const float* __restrict__ in, const float* __restrict__ w,
               const float* __restrict__ b, float* __restrict__ out)
{
    int token = blockIdx.x;
    int tid   = threadIdx.x;
    __shared__ float buf[16];

    float x[4];
    float s = 0.f, ss = 0.f;
#pragma unroll
    for (int i = 0; i < 4; i++) {
        float xv = in[(size_t)token * DDIM + tid + 256 * i];
        x[i] = xv; s += xv; ss += xv * xv;
    }
#pragma unroll
    for (int o = 16; o; o >>= 1) {
        s  += __shfl_xor_sync(0xffffffffu, s, o);
        ss += __shfl_xor_sync(0xffffffffu, ss, o);
    }
    int lane = tid & 31, wp = tid >> 5;
    __syncthreads();
    if (lane == 0) { buf[wp] = s; buf[8 + wp] = ss; }
    __syncthreads();
    float st = 0.f, sst = 0.f;
#pragma unroll
    for (int j = 0; j < 8; j++) { st += buf[j]; sst += buf[8 + j]; }
    float mu  = st * (1.0f / DDIM);
    float var = sst * (1.0f / DDIM) - mu * mu;
    float r   = rsqrtf(var + LN_EPS);
#pragma unroll
    for (int i = 0; i < 4; i++) {
        int d = tid + 256 * i;
        out[(size_t)token * DDIM + d] = (x[i] - mu) * r * w[d] + b[d];
    }
}

// ---------------- bf16x3 tensor-core GEMM ------------------------------------
// C[M,N] = A[M,K] @ B[N,K]^T + bias (+gelu)(+res)
// fp32 operands split into bf16 hi+lo; acc = hi*hi + hi*lo + lo*hi in fp32.
// Tile 128x128xBK32, 256 threads (8 warps as 2Mx4N, warp tile 64x32).

#define GBM 128
#define GBN 128
#define GBK 32
#define LROW 40                     // padded row length (bf16 elems) = 80 bytes
#define TILE_E (GBM * LROW)         // elems per split tile
#define BUF_BYTES (4 * TILE_E * 2)  // aHi,aLo,bHi,bLo  = 40960 B
#define GEMM_SMEM (2 * BUF_BYTES)   // 81920 B

__device__ __forceinline__ void ldsm4(unsigned &r0, unsigned &r1, unsigned &r2,
                                      unsigned &r3, unsigned addr) {
    asm volatile("ldmatrix.sync.aligned.m8n8.x4.shared.b16 {%0,%1,%2,%3}, [%4];"
                 : "=r"(r0), "=r"(r1), "=r"(r2), "=r"(r3) : "r"(addr));
}

__device__ __forceinline__ void mma16816(float* c, const unsigned* a, const unsigned* b) {
    asm volatile(
        "mma.sync.aligned.m16n8k16.row.col.f32.bf16.bf16.f32 "
        "{%0,%1,%2,%3},{%4,%5,%6,%7},{%8,%9},{%0,%1,%2,%3};"
        : "+f"(c[0]), "+f"(c[1]), "+f"(c[2]), "+f"(c[3])
        : "r"(a[0]), "r"(a[1]), "r"(a[2]), "r"(a[3]), "r"(b[0]), "r"(b[1]));
}

template<int ACT, bool RES>
__global__ __launch_bounds__(256)
void gemm_bf16x3(const float* __restrict__ A, const float* __restrict__ Bm,
                 const float* __restrict__ bias, const float* __restrict__ res,
                 float* __restrict__ C, int M, int N, int K)
{
    extern __shared__ char smem[];
    unsigned sbase = (unsigned)__cvta_generic_to_shared(smem);

    int tid  = threadIdx.x;
    int lane = tid & 31;
    int warp = tid >> 5;
    int wr   = warp >> 2;            // 0..1  (M)
    int wc   = warp & 3;             // 0..3  (N)

    int bm = blockIdx.y * GBM;
    int bn = blockIdx.x * GBN;

    // global staging: thread -> (row, 16-col half)
    int lrow = tid >> 1;             // 0..127
    int lch  = (tid & 1) * 16;       // 0 or 16
    const float* Ag = A  + (size_t)(bm + lrow) * K + lch;
    const float* Bg = Bm + (size_t)(bn + lrow) * K + lch;

    // smem byte offsets of the 4 split tiles within a buffer
    //   aHi: 0, aLo: TILE_E*2, bHi: 2*TILE_E*2, bLo: 3*TILE_E*2
    unsigned stsA = sbase + (lrow * LROW + lch) * 2;
    unsigned stsB = stsA + 2 * TILE_E * 2;

    // ldmatrix lane offsets (bytes)
    unsigned aLane = (unsigned)((lane & 15) * (LROW * 2) + ((lane >> 4) << 4));
    unsigned bLane = (unsigned)(((lane & 7) + ((lane >> 4) << 3)) * (LROW * 2)
                                + (((lane >> 3) & 1) << 4));
    unsigned aRd = sbase + wr * 64 * (LROW * 2) + aLane;
    unsigned bRd = sbase + 2 * TILE_E * 2 + wc * 32 * (LROW * 2) + bLane;

    float acc[4][4][4];
#pragma unroll
    for (int i = 0; i < 4; i++)
#pragma unroll
        for (int j = 0; j < 4; j++)
#pragma unroll
            for (int q = 0; q < 4; q++) acc[i][j][q] = 0.f;

    int nIter = K / GBK;

    float4 pa[4], pb[4];
#pragma unroll
    for (int i = 0; i < 4; i++) {
        pa[i] = *(const float4*)(Ag + 4 * i);
        pb[i] = *(const float4*)(Bg + 4 * i);
    }

    for (int it = 0; it < nIter; it++) {
        unsigned bufOff = (unsigned)((it & 1) * BUF_BYTES);

        // convert + store current regs to smem
        {
            __nv_bfloat16 __align__(16) ahv[16], alv[16], bhv[16], blv[16];
            const float* af = (const float*)pa;
            const float* bf = (const float*)pb;
#pragma unroll
            for (int j = 0; j < 16; j++) {
                float v = af[j];
                __nv_bfloat16 h = __float2bfloat16_rn(v);
                ahv[j] = h;
                alv[j] = __float2bfloat16_rn(v - __bfloat162float(h));
                float w = bf[j];
                __nv_bfloat16 g = __float2bfloat16_rn(w);
                bhv[j] = g;
                blv[j] = __float2bfloat16_rn(w - __bfloat162float(g));
            }
            unsigned a0 = stsA + bufOff;
            unsigned b0 = stsB + bufOff;
            asm volatile("st.shared.v4.b32 [%0], {%1,%2,%3,%4};" ::
                "r"(a0), "r"(((unsigned*)ahv)[0]), "r"(((unsigned*)ahv)[1]),
                "r"(((unsigned*)ahv)[2]), "r"(((unsigned*)ahv)[3]));
            asm volatile("st.shared.v4.b32 [%0], {%1,%2,%3,%4};" ::
                "r"(a0 + 16), "r"(((unsigned*)ahv)[4]), "r"(((unsigned*)ahv)[5]),
                "r"(((unsigned*)ahv)[6]), "r"(((unsigned*)ahv)[7]));
            asm volatile("st.shared.v4.b32 [%0], {%1,%2,%3,%4};" ::
                "r"(a0 + TILE_E * 2), "r"(((unsigned*)alv)[0]), "r"(((unsigned*)alv)[1]),
                "r"(((unsigned*)alv)[2]), "r"(((unsigned*)alv)[3]));
            asm volatile("st.shared.v4.b32 [%0], {%1,%2,%3,%4};" ::
                "r"(a0 + TILE_E * 2 + 16), "r"(((unsigned*)alv)[4]), "r"(((unsigned*)alv)[5]),
                "r"(((unsigned*)alv)[6]), "r"(((unsigned*)alv)[7]));
            asm volatile("st.shared.v4.b32 [%0], {%1,%2,%3,%4};" ::
                "r"(b0), "r"(((unsigned*)bhv)[0]), "r"(((unsigned*)bhv)[1]),
                "r"(((unsigned*)bhv)[2]), "r"(((unsigned*)bhv)[3]));
            asm volatile("st.shared.v4.b32 [%0], {%1,%2,%3,%4};" ::
                "r"(b0 + 16), "r"(((unsigned*)bhv)[4]), "r"(((unsigned*)bhv)[5]),
                "r"(((unsigned*)bhv)[6]), "r"(((unsigned*)bhv)[7]));
            asm volatile("st.shared.v4.b32 [%0], {%1,%2,%3,%4};" ::
                "r"(b0 + TILE_E * 2), "r"(((unsigned*)blv)[0]), "r"(((unsigned*)blv)[1]),
                "r"(((unsigned*)blv)[2]), "r"(((unsigned*)blv)[3]));
            asm volatile("st.shared.v4.b32 [%0], {%1,%2,%3,%4};" ::
                "r"(b0 + TILE_E * 2 + 16), "r"(((unsigned*)blv)[4]), "r"(((unsigned*)blv)[5]),
                "r"(((unsigned*)blv)[6]), "r"(((unsigned*)blv)[7]));
        }
        __syncthreads();

        // prefetch next tile
        if (it + 1 < nIter) {
            const float* An = Ag + (it + 1) * GBK;
            const float* Bn = Bg + (it + 1) * GBK;
#pragma unroll
            for (int i = 0; i < 4; i++) {
                pa[i] = *(const float4*)(An + 4 * i);
                pb[i] = *(const float4*)(Bn + 4 * i);
            }
        }

        // compute 2 k16 steps
#pragma unroll
        for (int ks = 0; ks < 2; ks++) {
            unsigned kb = bufOff + ks * 32;   // 16 bf16 = 32 bytes
            unsigned ah[4][4], al[4][4], bh[4][2], bl[4][2];
#pragma unroll
            for (int mt = 0; mt < 4; mt++) {
                unsigned ad = aRd + kb + mt * 16 * (LROW * 2);
                ldsm4(ah[mt][0], ah[mt][1], ah[mt][2], ah[mt][3], ad);
                ldsm4(al[mt][0], al[mt][1], al[mt][2], al[mt][3], ad + TILE_E * 2);
            }
#pragma unroll
            for (int np = 0; np < 2; np++) {
                unsigned bd = bRd + kb + np * 16 * (LROW * 2);
                ldsm4(bh[2*np][0], bh[2*np][1], bh[2*np+1][0], bh[2*np+1][1], bd);
                ldsm4(bl[2*np][0], bl[2*np][1], bl[2*np+1][0], bl[2*np+1][1], bd + TILE_E * 2);
            }
#pragma unroll
            for (int mt = 0; mt < 4; mt++)
#pragma unroll
                for (int nt = 0; nt < 4; nt++) {
                    mma16816(acc[mt][nt], ah[mt], bh[nt]);
                    mma16816(acc[mt][nt], ah[mt], bl[nt]);
                    mma16816(acc[mt][nt], al[mt], bh[nt]);
                }
        }
        __syncthreads();
    }

    // epilogue
    int rql = lane >> 2;
    int cpl = (lane & 3) * 2;
#pragma unroll
    for (int mt = 0; mt < 4; mt++) {
#pragma unroll
        for (int nt = 0; nt < 4; nt++) {
            int r0 = bm + wr * 64 + mt * 16 + rql;
            int c0 = bn + wc * 32 + nt * 8 + cpl;
            float b0 = bias[c0], b1 = bias[c0 + 1];
            float v00 = acc[mt][nt][0] + b0, v01 = acc[mt][nt][1] + b1;
            float v10 = acc[mt][nt][2] + b0, v11 = acc[mt][nt][3] + b1;
            if (ACT == 1) {
                v00 = gelu_exact(v00); v01 = gelu_exact(v01);
                v10 = gelu_exact(v10); v11 = gelu_exact(v11);
            }
            if (RES) {
                v00 += res[(size_t)r0 * N + c0];
                v01 += res[(size_t)r0 * N + c0 + 1];
                v10 += res[(size_t)(r0 + 8) * N + c0];
                v11 += res[(size_t)(r0 + 8) * N + c0 + 1];
            }
            *(float2*)&C[(size_t)r0 * N + c0]       = make_float2(v00, v01);
            *(float2*)&C[(size_t)(r0 + 8) * N + c0] = make_float2(v10, v11);
        }
    }
}

// ---------------- causal flash attention (fp32) -------------------------------
__global__ __launch_bounds__(256, 2)
void flash_kernel(const float* __restrict__ qkv, float* __restrict__ ctx)
{
    __shared__ float Ks[64][64];
    __shared__ float Vs[64][64];

    int qt  = blockIdx.x;
    int bh  = blockIdx.y;
    int b   = bh >> 4;
    int h   = bh & 15;
    int tid = threadIdx.x;
    int r   = tid >> 2;
    int c   = tid & 3;
    int qg  = qt * 64 + r;

    const float* qbase = qkv + ((size_t)b * TSEQ + qg) * (3 * DDIM) + h * HDIM + c * 16;
    float q[16];
#pragma unroll
    for (int i = 0; i < 16; i++) q[i] = qbase[i] * 0.125f;

    float m = -1e30f, l = 0.f;
    float acc[16];
#pragma unroll
    for (int i = 0; i < 16; i++) acc[i] = 0.f;

    int lane  = tid & 31;
    unsigned gmask = 0xFu << (lane & 28);

    int nkt = qt + 1;
    for (int kt = 0; kt < nkt; kt++) {
        __syncthreads();
        {
            int krow = kt * 64 + r;
            const float* kb = qkv + ((size_t)b * TSEQ + krow) * (3 * DDIM) + DDIM + h * HDIM + c * 16;
            const float* vb = kb + DDIM;
#pragma unroll
            for (int i = 0; i < 4; i++) {
                *(float4*)&Ks[r][c * 16 + 4 * i] = *(const float4*)(kb + 4 * i);
                *(float4*)&Vs[r][c * 16 + 4 * i] = *(const float4*)(vb + 4 * i);
            }
        }
        __syncthreads();

        int kmax = (kt == qt) ? (r + 1) : 64;
        for (int kk = 0; kk < kmax; kk++) {
            const float4* kr = (const float4*)&Ks[kk][c * 16];
            float4 k0 = kr[0], k1 = kr[1], k2 = kr[2], k3 = kr[3];
            float s = q[0]*k0.x + q[1]*k0.y + q[2]*k0.z + q[3]*k0.w
                    + q[4]*k1.x + q[5]*k1.y + q[6]*k1.z + q[7]*k1.w
                    + q[8]*k2.x + q[9]*k2.y + q[10]*k2.z + q[11]*k2.w
                    + q[12]*k3.x + q[13]*k3.y + q[14]*k3.z + q[15]*k3.w;
            s += __shfl_xor_sync(gmask, s, 1);
            s += __shfl_xor_sync(gmask, s, 2);

            float mn    = fmaxf(m, s);
            float scale = __expf(m - mn);
            float p     = __expf(s - mn);
            l = l * scale + p;
            m = mn;

            const float4* vr = (const float4*)&Vs[kk][c * 16];
            float4 v0 = vr[0], v1 = vr[1], v2 = vr[2], v3 = vr[3];
            acc[0]  = acc[0]*scale  + p*v0.x;  acc[1]  = acc[1]*scale  + p*v0.y;
            acc[2]  = acc[2]*scale  + p*v0.z;  acc[3]  = acc[3]*scale  + p*v0.w;
            acc[4]  = acc[4]*scale  + p*v1.x;  acc[5]  = acc[5]*scale  + p*v1.y;
            acc[6]  = acc[6]*scale  + p*v1.z;  acc[7]  = acc[7]*scale  + p*v1.w;
            acc[8]  = acc[8]*scale  + p*v2.x;  acc[9]  = acc[9]*scale  + p*v2.y;
            acc[10] = acc[10]*scale + p*v2.z;  acc[11] = acc[11]*scale + p*v2.w;
            acc[12] = acc[12]*scale + p*v3.x;  acc[13] = acc[13]*scale + p*v3.y;
            acc[14] = acc[14]*scale + p*v3.z;  acc[15] = acc[15]*scale + p*v3.w;
        }
    }

    float invl = 1.0f / l;
    float* ob = ctx + ((size_t)b * TSEQ + qg) * DDIM + h * HDIM + c * 16;
#pragma unroll
    for (int i = 0; i < 16; i++) ob[i] = acc[i] * invl;
}

// ---------------- driver ------------------------------------------------------
extern "C" void kernel_launch(void* const* d_in, const int* in_sizes, int n_in,
                              void* d_out, int out_size)
{
    const float* src        = (const float*)d_in[0];
    const float* w_attn     = (const float*)d_in[1];
    const float* rms_attn_w = (const float*)d_in[2];
    const float* w_ffn      = (const float*)d_in[3];
    const float* rms_ffn_w  = (const float*)d_in[4];
    const float* ln_attn_w  = (const float*)d_in[5];
    const float* ln_attn_b  = (const float*)d_in[6];
    const float* ln_ffn_w   = (const float*)d_in[7];
    const float* ln_ffn_b   = (const float*)d_in[8];
    const float* in_proj_w  = (const float*)d_in[9];
    const float* in_proj_b  = (const float*)d_in[10];
    const float* out_proj_w = (const float*)d_in[11];
    const float* out_proj_b = (const float*)d_in[12];
    const float* ffn_w1     = (const float*)d_in[13];
    const float* ffn_b1     = (const float*)d_in[14];
    const float* ffn_w2     = (const float*)d_in[15];
    const float* ffn_b2     = (const float*)d_in[16];
    float* out = (float*)d_out;

    float *hattn, *x, *qkv, *ctx, *vlat, *hmlp, *y, *ffn1;
    cudaGetSymbolAddress((void**)&hattn, g_hattn);
    cudaGetSymbolAddress((void**)&x,     g_x);
    cudaGetSymbolAddress((void**)&qkv,   g_qkv);
    cudaGetSymbolAddress((void**)&ctx,   g_ctx);
    cudaGetSymbolAddress((void**)&vlat,  g_vlat);
    cudaGetSymbolAddress((void**)&hmlp,  g_hmlp);
    cudaGetSymbolAddress((void**)&y,     g_y);
    cudaGetSymbolAddress((void**)&ffn1,  g_ffn1);

    cudaFuncSetAttribute(gemm_bf16x3<0, false>,
                         cudaFuncAttributeMaxDynamicSharedMemorySize, GEMM_SMEM);
    cudaFuncSetAttribute(gemm_bf16x3<0, true>,
                         cudaFuncAttributeMaxDynamicSharedMemorySize, GEMM_SMEM);
    cudaFuncSetAttribute(gemm_bf16x3<1, false>,
                         cudaFuncAttributeMaxDynamicSharedMemorySize, GEMM_SMEM);

    // 1) depth-softmax attention residual over the 6 sources
    far_kernel<6><<<BT, 256>>>(src, nullptr, w_attn, rms_attn_w, hattn);
    // 2) LN + QKV projection
    ln_kernel<<<BT, 256>>>(hattn, ln_attn_w, ln_attn_b, x);
    gemm_bf16x3<0, false><<<dim3(3 * DDIM / 128, BT / 128), 256, GEMM_SMEM>>>(
        x, in_proj_w, in_proj_b, nullptr, qkv, BT, 3 * DDIM, DDIM);
    // causal MHA
    flash_kernel<<<dim3(TSEQ / 64, BSZ * HNUM), 256>>>(qkv, ctx);
    // out projection + residual (v_prev = sources[-1])
    gemm_bf16x3<0, true><<<dim3(DDIM / 128, BT / 128), 256, GEMM_SMEM>>>(
        ctx, out_proj_w, out_proj_b, src + (size_t)(LNUM - 1) * BT * DDIM,
        vlat, BT, DDIM, DDIM);
    // 4) depth-softmax attention residual over 7 layers
    far_kernel<7><<<BT, 256>>>(src, vlat, w_ffn, rms_ffn_w, hmlp);
    // 5) LN + FFN (GELU) + final residual
    ln_kernel<<<BT, 256>>>(hmlp, ln_ffn_w, ln_ffn_b, y);
    gemm_bf16x3<1, false><<<dim3(DFF / 128, BT / 128), 256, GEMM_SMEM>>>(
        y, ffn_w1, ffn_b1, nullptr, ffn1, BT, DFF, DDIM);
    gemm_bf16x3<0, true><<<dim3(DDIM / 128, BT / 128), 256, GEMM_SMEM>>>(
        ffn1, ffn_w2, ffn_b2, vlat, out, BT, DDIM, DFF);
}

// round 3
// speedup vs baseline: 1.6214x; 1.0512x over previous
#include <cuda_runtime.h>
#include <cuda_bf16.h>
#include <math.h>

// Problem constants
#define LNUM 6
#define BSZ  4
#define TSEQ 1024
#define DDIM 1024
#define HNUM 16
#define HDIM 64
#define DFF  4096
#define BT   4096          // BSZ*TSEQ
#define RMS_EPS 1.1920929e-07f
#define LN_EPS  1e-5f

// ---------------- scratch (static device arrays; no allocations) -------------
__device__ float g_hattn[(size_t)BT * DDIM];
__device__ float g_qkv  [(size_t)BT * 3 * DDIM];
__device__ float g_vlat [(size_t)BT * DDIM];
__device__ float g_hmlp [(size_t)BT * DDIM];

// bf16 hi/lo planes (activations)
__device__ __nv_bfloat16 g_x_h [(size_t)BT * DDIM];
__device__ __nv_bfloat16 g_x_l [(size_t)BT * DDIM];
__device__ __nv_bfloat16 g_ctx_h[(size_t)BT * DDIM];
__device__ __nv_bfloat16 g_ctx_l[(size_t)BT * DDIM];
__device__ __nv_bfloat16 g_y_h [(size_t)BT * DDIM];
__device__ __nv_bfloat16 g_y_l [(size_t)BT * DDIM];
__device__ __nv_bfloat16 g_f1_h[(size_t)BT * DFF];
__device__ __nv_bfloat16 g_f1_l[(size_t)BT * DFF];

// bf16 hi/lo planes (weights)
__device__ __nv_bfloat16 g_wip_h[(size_t)3 * DDIM * DDIM];
__device__ __nv_bfloat16 g_wip_l[(size_t)3 * DDIM * DDIM];
__device__ __nv_bfloat16 g_wop_h[(size_t)DDIM * DDIM];
__device__ __nv_bfloat16 g_wop_l[(size_t)DDIM * DDIM];
__device__ __nv_bfloat16 g_w1_h [(size_t)DFF * DDIM];
__device__ __nv_bfloat16 g_w1_l [(size_t)DFF * DDIM];
__device__ __nv_bfloat16 g_w2_h [(size_t)DDIM * DFF];
__device__ __nv_bfloat16 g_w2_l [(size_t)DDIM * DFF];

__device__ __forceinline__ float gelu_exact(float v) {
    return 0.5f * v * (1.0f + erff(v * 0.70710678118654752f));
}

__device__ __forceinline__ void split1(float v, __nv_bfloat16& h, __nv_bfloat16& l) {
    h = __float2bfloat16_rn(v);
    l = __float2bfloat16_rn(v - __bfloat162float(h));
}

// ---------------- fp32 -> bf16 hi/lo split (weights) --------------------------
__global__ __launch_bounds__(256)
void split_kernel(const float* __restrict__ in, __nv_bfloat16* __restrict__ hi,
                  __nv_bfloat16* __restrict__ lo, int n4)
{
    int i = blockIdx.x * 256 + threadIdx.x;
    if (i >= n4) return;
    float4 v = ((const float4*)in)[i];
    __nv_bfloat16 __align__(8) h[4], l[4];
    split1(v.x, h[0], l[0]); split1(v.y, h[1], l[1]);
    split1(v.z, h[2], l[2]); split1(v.w, h[3], l[3]);
    *(uint2*)(hi + 4 * (size_t)i) = *(uint2*)h;
    *(uint2*)(lo + 4 * (size_t)i) = *(uint2*)l;
}

// ---------------- depth-softmax attention residual ---------------------------
template<int LC>
__global__ __launch_bounds__(256)
void far_kernel(const float* __restrict__ src, const float* __restrict__ extra,
                const float* __restrict__ proj, const float* __restrict__ rmsw,
                float* __restrict__ out)
{
    int token = blockIdx.x;
    int tid   = threadIdx.x;
    __shared__ float buf[16];

    float pw[4];
#pragma unroll
    for (int i = 0; i < 4; i++) {
        int d = tid + 256 * i;
        pw[i] = proj[d] * rmsw[d];
    }

    float v[LC][4];
    float logit[LC];

#pragma unroll
    for (int l = 0; l < LC; l++) {
        const float* p = (l < LNUM) ? (src + ((size_t)l * BT + token) * DDIM)
                                    : (extra + (size_t)token * DDIM);
        float ss = 0.f, dw = 0.f;
#pragma unroll
        for (int i = 0; i < 4; i++) {
            float xv = p[tid + 256 * i];
            v[l][i] = xv;
            ss += xv * xv;
            dw += pw[i] * xv;
        }
#pragma unroll
        for (int o = 16; o; o >>= 1) {
            ss += __shfl_xor_sync(0xffffffffu, ss, o);
            dw += __shfl_xor_sync(0xffffffffu, dw, o);
        }
        int lane = tid & 31, w = tid >> 5;
        __syncthreads();
        if (lane == 0) { buf[w] = ss; buf[8 + w] = dw; }
        __syncthreads();
        float sst = 0.f, dwt = 0.f;
#pragma unroll
        for (int j = 0; j < 8; j++) { sst += buf[j]; dwt += buf[8 + j]; }
        logit[l] = dwt * rsqrtf(sst * (1.0f / DDIM) + RMS_EPS);
    }

    float mx = logit[0];
#pragma unroll
    for (int l = 1; l < LC; l++) mx = fmaxf(mx, logit[l]);
    float s = 0.f;
    float wl[LC];
#pragma unroll
    for (int l = 0; l < LC; l++) { wl[l] = __expf(logit[l] - mx); s += wl[l]; }
    float inv = 1.0f / s;

#pragma unroll
    for (int i = 0; i < 4; i++) {
        float o = 0.f;
#pragma unroll
        for (int l = 0; l < LC; l++) o += wl[l] * v[l][i];
        out[(size_t)token * DDIM + tid + 256 * i] = o * inv;
    }
}

// ---------------- LayerNorm (fused hi/lo split output) -------------------------
__global__ __launch_bounds__(256)
void ln_kernel(const float* __restrict__ in, const float* __restrict__ w,
               const float* __restrict__ b, __nv_bfloat16* __restrict__ oh,
               __nv_bfloat16* __restrict__ ol)
{
    int token = blockIdx.x;
    int tid   = threadIdx.x;
    __shared__ float buf[16];

    float x[4];
    float s = 0.f, ss = 0.f;
#pragma unroll
    for (int i = 0; i < 4; i++) {
        float xv = in[(size_t)token * DDIM + tid + 256 * i];
        x[i] = xv; s += xv; ss += xv * xv;
    }
#pragma unroll
    for (int o = 16; o; o >>= 1) {
        s  += __shfl_xor_sync(0xffffffffu, s, o);
        ss += __shfl_xor_sync(0xffffffffu, ss, o);
    }
    int lane = tid & 31, wp = tid >> 5;
    __syncthreads();
    if (lane == 0) { buf[wp] = s; buf[8 + wp] = ss; }
    __syncthreads();
    float st = 0.f, sst = 0.f;
#pragma unroll
    for (int j = 0; j < 8; j++) { st += buf[j]; sst += buf[8 + j]; }
    float mu  = st * (1.0f / DDIM);
    float var = sst * (1.0f / DDIM) - mu * mu;
    float r   = rsqrtf(var + LN_EPS);
#pragma unroll
    for (int i = 0; i < 4; i++) {
        int d = tid + 256 * i;
        float v = (x[i] - mu) * r * w[d] + b[d];
        __nv_bfloat16 h, l;
        split1(v, h, l);
        oh[(size_t)token * DDIM + d] = h;
        ol[(size_t)token * DDIM + d] = l;
    }
}

// ---------------- bf16x3 tensor-core GEMM (pre-split operands) ----------------
// C[M,N] = A[M,K] @ B[N,K]^T + bias (+gelu)(+res); A,B given as hi/lo planes.
// Tile 128x128x32, 256 threads (8 warps 2Mx4N), cp.async 3-stage pipeline.

#define GBM 128
#define GBN 128
#define GBK 32
#define LROWB 80                         // padded row stride in bytes (40 bf16)
#define PLANE_B (128 * LROWB)            // 10240 B per plane per stage
#define STAGE_B (4 * PLANE_B)            // Ah,Al,Bh,Bl = 40960 B
#define NSTAGE 3
#define GEMM_SMEM (NSTAGE * STAGE_B)     // 122880 B

__device__ __forceinline__ void cp16(unsigned dst, const void* src) {
    asm volatile("cp.async.ca.shared.global [%0], [%1], 16;" :: "r"(dst), "l"(src));
}
__device__ __forceinline__ void cp_commit() {
    asm volatile("cp.async.commit_group;");
}
__device__ __forceinline__ void cp_wait2() {
    asm volatile("cp.async.wait_group 2;");
}

__device__ __forceinline__ void ldsm4(unsigned &r0, unsigned &r1, unsigned &r2,
                                      unsigned &r3, unsigned addr) {
    asm volatile("ldmatrix.sync.aligned.m8n8.x4.shared.b16 {%0,%1,%2,%3}, [%4];"
                 : "=r"(r0), "=r"(r1), "=r"(r2), "=r"(r3) : "r"(addr));
}

__device__ __forceinline__ void mma16816(float* c, const unsigned* a, const unsigned* b) {
    asm volatile(
        "mma.sync.aligned.m16n8k16.row.col.f32.bf16.bf16.f32 "
        "{%0,%1,%2,%3},{%4,%5,%6,%7},{%8,%9},{%0,%1,%2,%3};"
        : "+f"(c[0]), "+f"(c[1]), "+f"(c[2]), "+f"(c[3])
        : "r"(a[0]), "r"(a[1]), "r"(a[2]), "r"(a[3]), "r"(b[0]), "r"(b[1]));
}

template<int ACT, bool RES, bool OSPLIT>
__global__ __launch_bounds__(256)
void gemm_pair(const __nv_bfloat16* __restrict__ Ah, const __nv_bfloat16* __restrict__ Al,
               const __nv_bfloat16* __restrict__ Bh, const __nv_bfloat16* __restrict__ Bl,
               const float* __restrict__ bias, const float* __restrict__ res,
               float* __restrict__ C, __nv_bfloat16* __restrict__ Chi,
               __nv_bfloat16* __restrict__ Clo, int M, int N, int K)
{
    extern __shared__ char smem[];
    unsigned sbase = (unsigned)__cvta_generic_to_shared(smem);

    int tid  = threadIdx.x;
    int lane = tid & 31;
    int warp = tid >> 5;
    int wr   = warp >> 2;
    int wc   = warp & 3;

    int bm = blockIdx.y * GBM;
    int bn = blockIdx.x * GBN;

    // cp.async mapping: thread -> (row = tid>>1, 32B half = tid&1); 2 chunks/plane
    int lrow = tid >> 1;
    int lhalf = tid & 1;
    size_t aRowOff = (size_t)(bm + lrow) * K + lhalf * 16;
    size_t bRowOff = (size_t)(bn + lrow) * K + lhalf * 16;
    unsigned stBase = sbase + lrow * LROWB + lhalf * 32;

    // ldmatrix lane addressing (LROWB stride is conflict-free)
    unsigned aLane = (unsigned)((lane & 15) * LROWB + ((lane >> 4) << 4));
    unsigned bLane = (unsigned)(((lane & 7) + ((lane >> 4) << 3)) * LROWB
                                + (((lane >> 3) & 1) << 4));
    unsigned aRdB = sbase + wr * 64 * LROWB + aLane;
    unsigned bRdB = sbase + 2 * PLANE_B + wc * 32 * LROWB + bLane;

    float acc[4][4][4];
#pragma unroll
    for (int i = 0; i < 4; i++)
#pragma unroll
        for (int j = 0; j < 4; j++)
#pragma unroll
            for (int q = 0; q < 4; q++) acc[i][j][q] = 0.f;

    int nIter = K / GBK;

    auto issue = [&](int it, int stage) {
        int k0 = it * GBK;
        unsigned sb = stBase + stage * STAGE_B;
        const __nv_bfloat16* a0 = Ah + aRowOff + k0;
        const __nv_bfloat16* a1 = Al + aRowOff + k0;
        const __nv_bfloat16* b0 = Bh + bRowOff + k0;
        const __nv_bfloat16* b1 = Bl + bRowOff + k0;
        cp16(sb,                 a0);     cp16(sb + 16,                 a0 + 8);
        cp16(sb + PLANE_B,       a1);     cp16(sb + PLANE_B + 16,       a1 + 8);
        cp16(sb + 2 * PLANE_B,   b0);     cp16(sb + 2 * PLANE_B + 16,   b0 + 8);
        cp16(sb + 3 * PLANE_B,   b1);     cp16(sb + 3 * PLANE_B + 16,   b1 + 8);
        cp_commit();
    };

    issue(0, 0);
    issue(1, 1);

    for (int it = 0; it < nIter; it++) {
        if (it + 2 < nIter) issue(it + 2, (it + 2) % NSTAGE);
        cp_wait2();
        __syncthreads();

        unsigned stOff = (unsigned)((it % NSTAGE) * STAGE_B);
#pragma unroll
        for (int ks = 0; ks < 2; ks++) {
            unsigned kb = stOff + ks * 32;
            unsigned ah[4][4], al[4][4], bh[4][2], bl[4][2];
#pragma unroll
            for (int mt = 0; mt < 4; mt++) {
                unsigned ad = aRdB + kb + mt * 16 * LROWB;
                ldsm4(ah[mt][0], ah[mt][1], ah[mt][2], ah[mt][3], ad);
                ldsm4(al[mt][0], al[mt][1], al[mt][2], al[mt][3], ad + PLANE_B);
            }
#pragma unroll
            for (int np = 0; np < 2; np++) {
                unsigned bd = bRdB + kb + np * 16 * LROWB;
                ldsm4(bh[2*np][0], bh[2*np][1], bh[2*np+1][0], bh[2*np+1][1], bd);
                ldsm4(bl[2*np][0], bl[2*np][1], bl[2*np+1][0], bl[2*np+1][1], bd + PLANE_B);
            }
#pragma unroll
            for (int mt = 0; mt < 4; mt++)
#pragma unroll
                for (int nt = 0; nt < 4; nt++) {
                    mma16816(acc[mt][nt], ah[mt], bh[nt]);
                    mma16816(acc[mt][nt], ah[mt], bl[nt]);
                    mma16816(acc[mt][nt], al[mt], bh[nt]);
                }
        }
        __syncthreads();
    }

    // epilogue
    int rql = lane >> 2;
    int cpl = (lane & 3) * 2;
#pragma unroll
    for (int mt = 0; mt < 4; mt++) {
#pragma unroll
        for (int nt = 0; nt < 4; nt++) {
            int r0 = bm + wr * 64 + mt * 16 + rql;
            int c0 = bn + wc * 32 + nt * 8 + cpl;
            float b0 = bias[c0], b1 = bias[c0 + 1];
            float v00 = acc[mt][nt][0] + b0, v01 = acc[mt][nt][1] + b1;
            float v10 = acc[mt][nt][2] + b0, v11 = acc[mt][nt][3] + b1;
            if (ACT == 1) {
                v00 = gelu_exact(v00); v01 = gelu_exact(v01);
                v10 = gelu_exact(v10); v11 = gelu_exact(v11);
            }
            if (RES) {
                v00 += res[(size_t)r0 * N + c0];
                v01 += res[(size_t)r0 * N + c0 + 1];
                v10 += res[(size_t)(r0 + 8) * N + c0];
                v11 += res[(size_t)(r0 + 8) * N + c0 + 1];
            }
            if (OSPLIT) {
                __nv_bfloat16 __align__(4) h[2], l[2];
                split1(v00, h[0], l[0]); split1(v01, h[1], l[1]);
                *(unsigned*)(Chi + (size_t)r0 * N + c0) = *(unsigned*)h;
                *(unsigned*)(Clo + (size_t)r0 * N + c0) = *(unsigned*)l;
                split1(v10, h[0], l[0]); split1(v11, h[1], l[1]);
                *(unsigned*)(Chi + (size_t)(r0 + 8) * N + c0) = *(unsigned*)h;
                *(unsigned*)(Clo + (size_t)(r0 + 8) * N + c0) = *(unsigned*)l;
            } else {
                *(float2*)&C[(size_t)r0 * N + c0]       = make_float2(v00, v01);
                *(float2*)&C[(size_t)(r0 + 8) * N + c0] = make_float2(v10, v11);
            }
        }
    }
}

// ---------------- causal flash attention (fp32, hi/lo split output) ------------
__global__ __launch_bounds__(256, 2)
void flash_kernel(const float* __restrict__ qkv, __nv_bfloat16* __restrict__ ch,
                  __nv_bfloat16* __restrict__ cl)
{
    __shared__ float Ks[64][64];
    __shared__ float Vs[64][64];

    int qt  = blockIdx.x;
    int bh  = blockIdx.y;
    int b   = bh >> 4;
    int h   = bh & 15;
    int tid = threadIdx.x;
    int r   = tid >> 2;
    int c   = tid & 3;
    int qg  = qt * 64 + r;

    const float* qbase = qkv + ((size_t)b * TSEQ + qg) * (3 * DDIM) + h * HDIM + c * 16;
    float q[16];
#pragma unroll
    for (int i = 0; i < 16; i++) q[i] = qbase[i] * 0.125f;

    float m = -1e30f, l = 0.f;
    float acc[16];
#pragma unroll
    for (int i = 0; i < 16; i++) acc[i] = 0.f;

    int lane  = tid & 31;
    unsigned gmask = 0xFu << (lane & 28);

    int nkt = qt + 1;
    for (int kt = 0; kt < nkt; kt++) {
        __syncthreads();
        {
            int krow = kt * 64 + r;
            const float* kb = qkv + ((size_t)b * TSEQ + krow) * (3 * DDIM) + DDIM + h * HDIM + c * 16;
            const float* vb = kb + DDIM;
#pragma unroll
            for (int i = 0; i < 4; i++) {
                *(float4*)&Ks[r][c * 16 + 4 * i] = *(const float4*)(kb + 4 * i);
                *(float4*)&Vs[r][c * 16 + 4 * i] = *(const float4*)(vb + 4 * i);
            }
        }
        __syncthreads();

        int kmax = (kt == qt) ? (r + 1) : 64;
        for (int kk = 0; kk < kmax; kk++) {
            const float4* kr = (const float4*)&Ks[kk][c * 16];
            float4 k0 = kr[0], k1 = kr[1], k2 = kr[2], k3 = kr[3];
            float s = q[0]*k0.x + q[1]*k0.y + q[2]*k0.z + q[3]*k0.w
                    + q[4]*k1.x + q[5]*k1.y + q[6]*k1.z + q[7]*k1.w
                    + q[8]*k2.x + q[9]*k2.y + q[10]*k2.z + q[11]*k2.w
                    + q[12]*k3.x + q[13]*k3.y + q[14]*k3.z + q[15]*k3.w;
            s += __shfl_xor_sync(gmask, s, 1);
            s += __shfl_xor_sync(gmask, s, 2);

            float mn    = fmaxf(m, s);
            float scale = __expf(m - mn);
            float p     = __expf(s - mn);
            l = l * scale + p;
            m = mn;

            const float4* vr = (const float4*)&Vs[kk][c * 16];
            float4 v0 = vr[0], v1 = vr[1], v2 = vr[2], v3 = vr[3];
            acc[0]  = acc[0]*scale  + p*v0.x;  acc[1]  = acc[1]*scale  + p*v0.y;
            acc[2]  = acc[2]*scale  + p*v0.z;  acc[3]  = acc[3]*scale  + p*v0.w;
            acc[4]  = acc[4]*scale  + p*v1.x;  acc[5]  = acc[5]*scale  + p*v1.y;
            acc[6]  = acc[6]*scale  + p*v1.z;  acc[7]  = acc[7]*scale  + p*v1.w;
            acc[8]  = acc[8]*scale  + p*v2.x;  acc[9]  = acc[9]*scale  + p*v2.y;
            acc[10] = acc[10]*scale + p*v2.z;  acc[11] = acc[11]*scale + p*v2.w;
            acc[12] = acc[12]*scale + p*v3.x;  acc[13] = acc[13]*scale + p*v3.y;
            acc[14] = acc[14]*scale + p*v3.z;  acc[15] = acc[15]*scale + p*v3.w;
        }
    }

    float invl = 1.0f / l;
    size_t ob = ((size_t)b * TSEQ + qg) * DDIM + h * HDIM + c * 16;
#pragma unroll
    for (int i = 0; i < 16; i++) {
        __nv_bfloat16 h2, l2;
        split1(acc[i] * invl, h2, l2);
        ch[ob + i] = h2;
        cl[ob + i] = l2;
    }
}

// ---------------- driver ------------------------------------------------------
extern "C" void kernel_launch(void* const* d_in, const int* in_sizes, int n_in,
                              void* d_out, int out_size)
{
    const float* src        = (const float*)d_in[0];
    const float* w_attn     = (const float*)d_in[1];
    const float* rms_attn_w = (const float*)d_in[2];
    const float* w_ffn      = (const float*)d_in[3];
    const float* rms_ffn_w  = (const float*)d_in[4];
    const float* ln_attn_w  = (const float*)d_in[5];
    const float* ln_attn_b  = (const float*)d_in[6];
    const float* ln_ffn_w   = (const float*)d_in[7];
    const float* ln_ffn_b   = (const float*)d_in[8];
    const float* in_proj_w  = (const float*)d_in[9];
    const float* in_proj_b  = (const float*)d_in[10];
    const float* out_proj_w = (const float*)d_in[11];
    const float* out_proj_b = (const float*)d_in[12];
    const float* ffn_w1     = (const float*)d_in[13];
    const float* ffn_b1     = (const float*)d_in[14];
    const float* ffn_w2     = (const float*)d_in[15];
    const float* ffn_b2     = (const float*)d_in[16];
    float* out = (float*)d_out;

    float *hattn, *qkv, *vlat, *hmlp;
    cudaGetSymbolAddress((void**)&hattn, g_hattn);
    cudaGetSymbolAddress((void**)&qkv,   g_qkv);
    cudaGetSymbolAddress((void**)&vlat,  g_vlat);
    cudaGetSymbolAddress((void**)&hmlp,  g_hmlp);

    __nv_bfloat16 *xh, *xl, *ctxh, *ctxl, *yh, *yl, *f1h, *f1l;
    __nv_bfloat16 *wiph, *wipl, *woph, *wopl, *w1h, *w1l, *w2h, *w2l;
    cudaGetSymbolAddress((void**)&xh,   g_x_h);   cudaGetSymbolAddress((void**)&xl,   g_x_l);
    cudaGetSymbolAddress((void**)&ctxh, g_ctx_h); cudaGetSymbolAddress((void**)&ctxl, g_ctx_l);
    cudaGetSymbolAddress((void**)&yh,   g_y_h);   cudaGetSymbolAddress((void**)&yl,   g_y_l);
    cudaGetSymbolAddress((void**)&f1h,  g_f1_h);  cudaGetSymbolAddress((void**)&f1l,  g_f1_l);
    cudaGetSymbolAddress((void**)&wiph, g_wip_h); cudaGetSymbolAddress((void**)&wipl, g_wip_l);
    cudaGetSymbolAddress((void**)&woph, g_wop_h); cudaGetSymbolAddress((void**)&wopl, g_wop_l);
    cudaGetSymbolAddress((void**)&w1h,  g_w1_h);  cudaGetSymbolAddress((void**)&w1l,  g_w1_l);
    cudaGetSymbolAddress((void**)&w2h,  g_w2_h);  cudaGetSymbolAddress((void**)&w2l,  g_w2_l);

    cudaFuncSetAttribute(gemm_pair<0, false, false>,
                         cudaFuncAttributeMaxDynamicSharedMemorySize, GEMM_SMEM);
    cudaFuncSetAttribute(gemm_pair<0, true, false>,
                         cudaFuncAttributeMaxDynamicSharedMemorySize, GEMM_SMEM);
    cudaFuncSetAttribute(gemm_pair<1, false, true>,
                         cudaFuncAttributeMaxDynamicSharedMemorySize, GEMM_SMEM);

    // 0) split weights into bf16 hi/lo planes
    split_kernel<<<(3 * DDIM * DDIM / 4 + 255) / 256, 256>>>(in_proj_w,  wiph, wipl, 3 * DDIM * DDIM / 4);
    split_kernel<<<(DDIM * DDIM / 4 + 255) / 256, 256>>>(out_proj_w, woph, wopl, DDIM * DDIM / 4);
    split_kernel<<<(DFF * DDIM / 4 + 255) / 256, 256>>>(ffn_w1, w1h, w1l, DFF * DDIM / 4);
    split_kernel<<<(DDIM * DFF / 4 + 255) / 256, 256>>>(ffn_w2, w2h, w2l, DDIM * DFF / 4);

    // 1) depth-softmax attention residual over the 6 sources
    far_kernel<6><<<BT, 256>>>(src, nullptr, w_attn, rms_attn_w, hattn);
    // 2) LN (split output) + QKV projection
    ln_kernel<<<BT, 256>>>(hattn, ln_attn_w, ln_attn_b, xh, xl);
    gemm_pair<0, false, false><<<dim3(3 * DDIM / 128, BT / 128), 256, GEMM_SMEM>>>(
        xh, xl, wiph, wipl, in_proj_b, nullptr, qkv, nullptr, nullptr,
        BT, 3 * DDIM, DDIM);
    // causal MHA (split output)
    flash_kernel<<<dim3(TSEQ / 64, BSZ * HNUM), 256>>>(qkv, ctxh, ctxl);
    // out projection + residual (v_prev = sources[-1])
    gemm_pair<0, true, false><<<dim3(DDIM / 128, BT / 128), 256, GEMM_SMEM>>>(
        ctxh, ctxl, woph, wopl, out_proj_b, src + (size_t)(LNUM - 1) * BT * DDIM,
        vlat, nullptr, nullptr, BT, DDIM, DDIM);
    // 4) depth-softmax attention residual over 7 layers
    far_kernel<7><<<BT, 256>>>(src, vlat, w_ffn, rms_ffn_w, hmlp);
    // 5) LN (split output) + FFN (GELU, split output) + final residual
    ln_kernel<<<BT, 256>>>(hmlp, ln_ffn_w, ln_ffn_b, yh, yl);
    gemm_pair<1, false, true><<<dim3(DFF / 128, BT / 128), 256, GEMM_SMEM>>>(
        yh, yl, w1h, w1l, ffn_b1, nullptr, nullptr, f1h, f1l, BT, DFF, DDIM);
    gemm_pair<0, true, false><<<dim3(DDIM / 128, BT / 128), 256, GEMM_SMEM>>>(
        f1h, f1l, w2h, w2l, ffn_b2, vlat, out, nullptr, nullptr, BT, DDIM, DFF);
}